// round 12
// baseline (speedup 1.0000x reference)
#include <cuda_runtime.h>

// LatticeSnake: B=16, N=48, K=7, PAD=3. Reference scatters 48 acids + 47
// inters into a 195^3 lattice (in-order, last-write-wins), extracts a 7^3
// window at each acid's idx2, masks by mask[n].
//
// FINAL (= R7, the measured-best of 8 passing variants): all-pairs
// candidate x window scatter. Window buffer stores only the winning candidate
// index (+1) as 32-bit int; atomicMax over scatter index == last-write-wins
// ordering; value looked up from cand[] at store time. WPC=4, 256 threads,
// grid 12x16 = 192 CTAs (single wave), float2-vectorized store.
//
// Convergence evidence (R3-R11): all pipes <5% of peak, issue <17%; bench dur
// pinned in a 6.40-6.88us band uncorrelated with ncu kernel time
// (4.48-5.28us). The residual is launch ramp (~5000 cyc) + cold-memory round
// trip + graph-replay overhead — outside the .cu's control. This config had
// the lowest kernel time (4.48us).
//
// mask is int32 (harness materializes JAX bool as 4-byte ints).

#define NACID   48
#define KWIN    7
#define PADW    3
#define CELLS   (KWIN * KWIN * KWIN)   // 343
#define NCAND   (2 * NACID - 1)        // 95
#define WPC     4                      // windows per CTA
#define SLICES  (NACID / WPC)          // 12
#define NTHREADS 256

__global__ __launch_bounds__(NTHREADS)
void lattice_snake_kernel(const float* __restrict__ acids,
                          const int* __restrict__ mask,
                          const int* __restrict__ idx,
                          float* __restrict__ out)
{
    __shared__ __align__(16) int buf[WPC * CELLS];  // winner cand index + 1 (0 = empty)
    __shared__ int4  cand[NCAND];                   // cx, cy, cz, value bits
    __shared__ int   wbase[WPC][3];
    __shared__ float wmask[WPC];

    const int slice = blockIdx.x;      // 0..11
    const int b     = blockIdx.y;      // 0..15
    const int t     = threadIdx.x;

    const int*   idxb = idx   + b * NACID * 3;
    const float* ab   = acids + b * NACID;
    const int*   mb   = mask  + b * NACID;

    // ---- stage 1: zero buffer (int4), build candidates, window bases ----
    {
        int4* bz = (int4*)buf;
        #pragma unroll
        for (int c = t; c < (WPC * CELLS) / 4; c += NTHREADS)
            bz[c] = make_int4(0, 0, 0, 0);
    }

    if (t < NCAND) {
        int cx, cy, cz, live;
        float v;
        if (t < NACID) {
            cx = 2 * idxb[3 * t + 0] + 94 + PADW;
            cy = 2 * idxb[3 * t + 1] + 94 + PADW;
            cz = 2 * idxb[3 * t + 2] + 94 + PADW;
            live = mb[t];
            v = ab[t];
        } else {
            const int j = t - NACID;   // 0..46
            cx = idxb[3 * j + 0] + idxb[3 * (j + 1) + 0] + 94 + PADW;
            cy = idxb[3 * j + 1] + idxb[3 * (j + 1) + 1] + 94 + PADW;
            cz = idxb[3 * j + 2] + idxb[3 * (j + 1) + 2] + 94 + PADW;
            live = mb[j + 1];
            v = ab[j] + ab[j + 1] + 1.0f;
        }
        if (!live) cx = 1 << 20;       // out of unsigned<7 range -> never hits
        cand[t] = make_int4(cx, cy, cz, __float_as_int(v));
    } else if (t >= 128 && t < 128 + WPC) {
        const int w = t - 128;
        const int n = slice * WPC + w;
        wbase[w][0] = 2 * idxb[3 * n + 0] + 94;
        wbase[w][1] = 2 * idxb[3 * n + 1] + 94;
        wbase[w][2] = 2 * idxb[3 * n + 2] + 94;
        wmask[w] = mb[n] ? 1.0f : 0.0f;
    }
    __syncthreads();

    // ---- stage 2: all-pairs candidate x window scatter (380 pairs) ----
    #pragma unroll
    for (int p = t; p < WPC * NCAND; p += NTHREADS) {
        const int w = p / NCAND;
        const int i = p - w * NCAND;
        const int4 c = cand[i];
        const int dx = c.x - wbase[w][0];
        const int dy = c.y - wbase[w][1];
        const int dz = c.z - wbase[w][2];
        if ((unsigned)dx < KWIN && (unsigned)dy < KWIN && (unsigned)dz < KWIN)
            atomicMax(&buf[w * CELLS + dx * 49 + dy * 7 + dz], i + 1);
    }
    __syncthreads();

    // ---- stage 3: float2-vectorized contiguous store (1372 floats) ----
    float2* outb = (float2*)(out + (b * NACID + slice * WPC) * CELLS);
    #pragma unroll
    for (int c2 = t; c2 < (WPC * CELLS) / 2; c2 += NTHREADS) {
        const int c = 2 * c2;
        const int i0 = buf[c];
        const int i1 = buf[c + 1];
        float2 v;
        v.x = i0 ? __int_as_float(cand[i0 - 1].w) * wmask[c / CELLS] : 0.0f;
        v.y = i1 ? __int_as_float(cand[i1 - 1].w) * wmask[(c + 1) / CELLS] : 0.0f;
        outb[c2] = v;
    }
}

extern "C" void kernel_launch(void* const* d_in, const int* in_sizes, int n_in,
                              void* d_out, int out_size)
{
    const float* acids = (const float*)d_in[0];   // (B, N) float32
    const int*   mask  = (const int*)d_in[1];     // (B, N) bool -> int32
    const int*   idx   = (const int*)d_in[2];     // (B, N, 3) int32
    float*       out   = (float*)d_out;           // (B, N, 7,7,7, 1) float32

    dim3 grid(SLICES, 16);
    lattice_snake_kernel<<<grid, NTHREADS>>>(acids, mask, idx, out);
}